// round 1
// baseline (speedup 1.0000x reference)
#include <cuda_runtime.h>
#include <math.h>

#define BATCH 16
#define CH    128
#define NPIX  4096
#define M3    384
#define NHEAD 4
#define HDIM  32
#define SCALE 0.17677669529663687f   // 1/sqrt(32)
#define EPSV  1e-5f

// ---------------- scratch (device globals; no allocation allowed) ----------------
__device__ float g_qkv[BATCH * M3 * NPIX];            // 96 MB: qkv (q rows overwritten by q_softmax)
__device__ float g_pre[BATCH * CH * NPIX];            // 32 MB: pre-norm output
__device__ float g_skv[BATCH * NHEAD * HDIM * HDIM];  // sum_n exp(k[d,n]) * v[e,n]
__device__ float g_sk [BATCH * NHEAD * HDIM];         // sum_n exp(k[d,n])
__device__ float g_M  [BATCH * CH * CH];              // fused  w_out @ blockdiag(ctx^T)
__device__ float g_stats[BATCH * 2];                  // per-batch sum, sumsq

// ---------------- K0: zero accumulators (graph-replay safe) ----------------
__global__ void k_zero() {
    int i = blockIdx.x * 256 + threadIdx.x;
    if (i < BATCH * NHEAD * HDIM * HDIM) g_skv[i] = 0.f;
    if (i < BATCH * NHEAD * HDIM)        g_sk[i]  = 0.f;
    if (i < BATCH * 2)                   g_stats[i] = 0.f;
}

// ---------------- K1: qkv = w_qkv(384x128) @ x[b](128x4096) ----------------
// 128x128 block tile, BK=16, 256 threads, 8x8 register micro-tile.
__global__ void __launch_bounds__(256) k_gemm_qkv(const float* __restrict__ W,
                                                  const float* __restrict__ X) {
    __shared__ float As[16][128];
    __shared__ float Bs[16][128];
    const int b  = blockIdx.z;
    const int m0 = blockIdx.y * 128;
    const int n0 = blockIdx.x * 128;
    const int tid = threadIdx.x;
    const int tx = tid & 15, ty = tid >> 4;
    const float* Xb = X + (size_t)b * CH * NPIX;

    float acc[8][8];
    #pragma unroll
    for (int i = 0; i < 8; i++)
        #pragma unroll
        for (int j = 0; j < 8; j++) acc[i][j] = 0.f;

    for (int k0 = 0; k0 < CH; k0 += 16) {
        #pragma unroll
        for (int l = 0; l < 2; l++) {            // A tile: 128 rows x 16 k, 512 float4
            int idx = tid + l * 256;
            int r = idx >> 2;
            int c4 = (idx & 3) << 2;
            float4 v = *reinterpret_cast<const float4*>(&W[(size_t)(m0 + r) * CH + k0 + c4]);
            As[c4 + 0][r] = v.x; As[c4 + 1][r] = v.y; As[c4 + 2][r] = v.z; As[c4 + 3][r] = v.w;
        }
        #pragma unroll
        for (int l = 0; l < 2; l++) {            // B tile: 16 k x 128 n
            int idx = tid + l * 256;
            int r = idx >> 5;
            int c4 = (idx & 31) << 2;
            *reinterpret_cast<float4*>(&Bs[r][c4]) =
                *reinterpret_cast<const float4*>(&Xb[(size_t)(k0 + r) * NPIX + n0 + c4]);
        }
        __syncthreads();
        #pragma unroll
        for (int kk = 0; kk < 16; kk++) {
            float a[8], bb[8];
            *reinterpret_cast<float4*>(a)      = *reinterpret_cast<float4*>(&As[kk][ty * 8]);
            *reinterpret_cast<float4*>(a + 4)  = *reinterpret_cast<float4*>(&As[kk][ty * 8 + 4]);
            *reinterpret_cast<float4*>(bb)     = *reinterpret_cast<float4*>(&Bs[kk][tx * 8]);
            *reinterpret_cast<float4*>(bb + 4) = *reinterpret_cast<float4*>(&Bs[kk][tx * 8 + 4]);
            #pragma unroll
            for (int i = 0; i < 8; i++)
                #pragma unroll
                for (int j = 0; j < 8; j++)
                    acc[i][j] = fmaf(a[i], bb[j], acc[i][j]);
        }
        __syncthreads();
    }
    float* out = g_qkv + (size_t)b * M3 * NPIX;
    #pragma unroll
    for (int i = 0; i < 8; i++) {
        int m = m0 + ty * 8 + i;
        #pragma unroll
        for (int j = 0; j < 8; j += 4) {
            float4 v = make_float4(acc[i][j], acc[i][j + 1], acc[i][j + 2], acc[i][j + 3]);
            *reinterpret_cast<float4*>(&out[(size_t)m * NPIX + n0 + tx * 8 + j]) = v;
        }
    }
}

// ---------------- K2: q softmax over d (32), *scale, in-place ----------------
__global__ void k_qsoftmax() {
    int nt = blockIdx.x, h = blockIdx.y, b = blockIdx.z;
    int n = nt * 256 + threadIdx.x;
    float* base = g_qkv + ((size_t)b * M3 + h * HDIM) * NPIX + n;
    float v[HDIM];
    float mx = -1e30f;
    #pragma unroll
    for (int d = 0; d < HDIM; d++) { v[d] = base[(size_t)d * NPIX]; mx = fmaxf(mx, v[d]); }
    float s = 0.f;
    #pragma unroll
    for (int d = 0; d < HDIM; d++) { v[d] = expf(v[d] - mx); s += v[d]; }
    float inv = SCALE / s;
    #pragma unroll
    for (int d = 0; d < HDIM; d++) base[(size_t)d * NPIX] = v[d] * inv;
}

// ---------------- K3: accumulate S_kv[d,e]=sum exp(k)*v ; S_k[d]=sum exp(k) ----------------
__global__ void __launch_bounds__(256) k_context() {
    __shared__ float Ek[HDIM][129];
    __shared__ float Vs[HDIM][129];
    int nt = blockIdx.x, h = blockIdx.y, b = blockIdx.z;
    int n0 = nt * 128;
    const float* kbase = g_qkv + ((size_t)b * M3 + CH     + h * HDIM) * NPIX + n0;
    const float* vbase = g_qkv + ((size_t)b * M3 + 2 * CH + h * HDIM) * NPIX + n0;
    int tid = threadIdx.x;
    for (int i = tid; i < HDIM * 128; i += 256) {
        int d = i >> 7, c = i & 127;
        Ek[d][c] = expf(kbase[(size_t)d * NPIX + c]);
        Vs[d][c] = vbase[(size_t)d * NPIX + c];
    }
    __syncthreads();
    int d  = tid >> 3;
    int e0 = (tid & 7) << 2;
    float a0 = 0.f, a1 = 0.f, a2 = 0.f, a3 = 0.f;
    #pragma unroll 4
    for (int c = 0; c < 128; c++) {
        float ek = Ek[d][c];
        a0 = fmaf(ek, Vs[e0 + 0][c], a0);
        a1 = fmaf(ek, Vs[e0 + 1][c], a1);
        a2 = fmaf(ek, Vs[e0 + 2][c], a2);
        a3 = fmaf(ek, Vs[e0 + 3][c], a3);
    }
    float* dst = g_skv + (((size_t)b * NHEAD + h) * HDIM + d) * HDIM + e0;
    atomicAdd(dst + 0, a0); atomicAdd(dst + 1, a1);
    atomicAdd(dst + 2, a2); atomicAdd(dst + 3, a3);
    if (tid < HDIM) {
        float s = 0.f;
        #pragma unroll 4
        for (int c = 0; c < 128; c++) s += Ek[tid][c];
        atomicAdd(&g_sk[((size_t)b * NHEAD + h) * HDIM + tid], s);
    }
}

// ---------------- K3b: M_b = w_out @ blockdiag(ctx_h^T), ctx = S_kv/S_k ----------------
__global__ void k_buildM(const float* __restrict__ Wout) {
    __shared__ float ctx[NHEAD * HDIM * HDIM];
    int b = blockIdx.x;
    int tid = threadIdx.x;
    for (int i = tid; i < NHEAD * HDIM * HDIM; i += 256)
        ctx[i] = g_skv[(size_t)b * NHEAD * HDIM * HDIM + i] /
                 g_sk[(size_t)b * NHEAD * HDIM + (i >> 5)];
    __syncthreads();
    for (int i = tid; i < CH * CH; i += 256) {
        int c = i >> 7, dg = i & 127;
        int h = dg >> 5, d = dg & 31;
        const float* wrow = Wout + (size_t)c * CH + h * HDIM;
        const float* cr   = ctx + (h * HDIM + d) * HDIM;
        float acc = 0.f;
        #pragma unroll
        for (int e = 0; e < HDIM; e++) acc = fmaf(wrow[e], cr[e], acc);
        g_M[(size_t)b * CH * CH + i] = acc;
    }
}

// ---------------- K4: pre = M_b(128x128) @ q_sm(128x4096) + b_out ; stats ----------------
__global__ void __launch_bounds__(256) k_proj(const float* __restrict__ Bias) {
    __shared__ float As[16][128];
    __shared__ float Bs[16][128];
    __shared__ float s1[8], s2[8];
    const int b  = blockIdx.y;
    const int n0 = blockIdx.x * 128;
    const int tid = threadIdx.x;
    const int tx = tid & 15, ty = tid >> 4;
    const float* W  = g_M + (size_t)b * CH * CH;
    const float* Qb = g_qkv + (size_t)b * M3 * NPIX;   // rows 0..127 are q_softmax

    float acc[8][8];
    #pragma unroll
    for (int i = 0; i < 8; i++)
        #pragma unroll
        for (int j = 0; j < 8; j++) acc[i][j] = 0.f;

    for (int k0 = 0; k0 < CH; k0 += 16) {
        #pragma unroll
        for (int l = 0; l < 2; l++) {
            int idx = tid + l * 256;
            int r = idx >> 2;
            int c4 = (idx & 3) << 2;
            float4 v = *reinterpret_cast<const float4*>(&W[(size_t)r * CH + k0 + c4]);
            As[c4 + 0][r] = v.x; As[c4 + 1][r] = v.y; As[c4 + 2][r] = v.z; As[c4 + 3][r] = v.w;
        }
        #pragma unroll
        for (int l = 0; l < 2; l++) {
            int idx = tid + l * 256;
            int r = idx >> 5;
            int c4 = (idx & 31) << 2;
            *reinterpret_cast<float4*>(&Bs[r][c4]) =
                *reinterpret_cast<const float4*>(&Qb[(size_t)(k0 + r) * NPIX + n0 + c4]);
        }
        __syncthreads();
        #pragma unroll
        for (int kk = 0; kk < 16; kk++) {
            float a[8], bb[8];
            *reinterpret_cast<float4*>(a)      = *reinterpret_cast<float4*>(&As[kk][ty * 8]);
            *reinterpret_cast<float4*>(a + 4)  = *reinterpret_cast<float4*>(&As[kk][ty * 8 + 4]);
            *reinterpret_cast<float4*>(bb)     = *reinterpret_cast<float4*>(&Bs[kk][tx * 8]);
            *reinterpret_cast<float4*>(bb + 4) = *reinterpret_cast<float4*>(&Bs[kk][tx * 8 + 4]);
            #pragma unroll
            for (int i = 0; i < 8; i++)
                #pragma unroll
                for (int j = 0; j < 8; j++)
                    acc[i][j] = fmaf(a[i], bb[j], acc[i][j]);
        }
        __syncthreads();
    }

    float* out = g_pre + (size_t)b * CH * NPIX;
    float lsum = 0.f, lsq = 0.f;
    #pragma unroll
    for (int i = 0; i < 8; i++) {
        int m = ty * 8 + i;
        float bias = Bias[m];
        #pragma unroll
        for (int j = 0; j < 8; j++) {
            float v = acc[i][j] + bias;
            acc[i][j] = v;
            lsum += v;
            lsq  = fmaf(v, v, lsq);
        }
        #pragma unroll
        for (int j = 0; j < 8; j += 4) {
            float4 v = make_float4(acc[i][j], acc[i][j + 1], acc[i][j + 2], acc[i][j + 3]);
            *reinterpret_cast<float4*>(&out[(size_t)m * NPIX + n0 + tx * 8 + j]) = v;
        }
    }
    // block-level reduction of stats
    #pragma unroll
    for (int off = 16; off > 0; off >>= 1) {
        lsum += __shfl_down_sync(0xffffffffu, lsum, off);
        lsq  += __shfl_down_sync(0xffffffffu, lsq,  off);
    }
    int warp = tid >> 5, lane = tid & 31;
    if (lane == 0) { s1[warp] = lsum; s2[warp] = lsq; }
    __syncthreads();
    if (tid == 0) {
        float t1 = 0.f, t2 = 0.f;
        #pragma unroll
        for (int w = 0; w < 8; w++) { t1 += s1[w]; t2 += s2[w]; }
        atomicAdd(&g_stats[b * 2 + 0], t1);
        atomicAdd(&g_stats[b * 2 + 1], t2);
    }
}

// ---------------- K5: LayerNorm normalize + affine ----------------
__global__ void k_norm(const float* __restrict__ gnw, const float* __restrict__ gnb,
                       float* __restrict__ out) {
    size_t i4 = (size_t)blockIdx.x * 256 + threadIdx.x;   // float4 index
    size_t idx = i4 * 4;
    const float invCN = 1.f / (float)(CH * NPIX);
    int b = (int)(idx / ((size_t)CH * NPIX));
    int c = (int)((idx / NPIX) & (CH - 1));
    float mean = g_stats[b * 2 + 0] * invCN;
    float var  = g_stats[b * 2 + 1] * invCN - mean * mean;
    float rstd = rsqrtf(var + EPSV);
    float w  = gnw[c] * rstd;
    float bb = gnb[c] - mean * w;
    float4 v = *reinterpret_cast<const float4*>(g_pre + idx);
    v.x = fmaf(v.x, w, bb);
    v.y = fmaf(v.y, w, bb);
    v.z = fmaf(v.z, w, bb);
    v.w = fmaf(v.w, w, bb);
    *reinterpret_cast<float4*>(out + idx) = v;
}

// ---------------- launcher ----------------
extern "C" void kernel_launch(void* const* d_in, const int* in_sizes, int n_in,
                              void* d_out, int out_size) {
    const float* x     = (const float*)d_in[0];
    const float* w_qkv = (const float*)d_in[1];
    const float* w_out = (const float*)d_in[2];
    const float* b_out = (const float*)d_in[3];
    const float* gnw   = (const float*)d_in[4];
    const float* gnb   = (const float*)d_in[5];

    k_zero<<<256, 256>>>();
    k_gemm_qkv<<<dim3(32, 3, 16), 256>>>(w_qkv, x);
    k_qsoftmax<<<dim3(16, 4, 16), 256>>>();
    k_context<<<dim3(32, 4, 16), 256>>>();
    k_buildM<<<16, 256>>>(w_out);
    k_proj<<<dim3(32, 16), 256>>>(b_out);
    k_norm<<<8192, 256>>>(gnw, gnb, (float*)d_out);
}

// round 2
// speedup vs baseline: 1.8376x; 1.8376x over previous
#include <cuda_runtime.h>
#include <math.h>

#define BATCH 16
#define CH    128
#define NPIX  4096
#define M3    384
#define NHEAD 4
#define HDIM  32
#define SCALE 0.17677669529663687f   // 1/sqrt(32)
#define EPSV  1e-5f
#define NCHUNK 16                     // k_context column chunks (4096/256)

// ---------------- scratch (device globals) ----------------
__device__ float g_qkv[BATCH * M3 * NPIX];            // q raw | exp(k) | v
__device__ float g_pre[BATCH * CH * NPIX];            // pre-norm output
__device__ float g_skvp[NCHUNK * BATCH * NHEAD * HDIM * HDIM]; // partial sum exp(k)*v
__device__ float g_skp [NCHUNK * BATCH * NHEAD * HDIM];        // partial sum exp(k)
__device__ float g_M  [BATCH * CH * CH];              // w_out @ blockdiag(ctx^T)
__device__ float g_stats[BATCH * 2];                  // per-batch sum, sumsq

// ---------------- helpers ----------------
__device__ __forceinline__ unsigned f2tf(float x) {
    unsigned u;
    asm("cvt.rna.tf32.f32 %0, %1;" : "=r"(u) : "f"(x));
    return u;
}
__device__ __forceinline__ void mma_tf32(float* c, const unsigned* a, const unsigned* b) {
    asm volatile("mma.sync.aligned.m16n8k8.row.col.f32.tf32.tf32.f32 "
                 "{%0,%1,%2,%3}, {%4,%5,%6,%7}, {%8,%9}, {%0,%1,%2,%3};"
                 : "+f"(c[0]), "+f"(c[1]), "+f"(c[2]), "+f"(c[3])
                 : "r"(a[0]), "r"(a[1]), "r"(a[2]), "r"(a[3]),
                   "r"(b[0]), "r"(b[1]));
}

// ---------------- K0: zero stats ----------------
__global__ void k_zero() {
    if (threadIdx.x < BATCH * 2) g_stats[threadIdx.x] = 0.f;
}

// ---------------- K1: qkv = w_qkv @ x[b]  (tf32 mma, 128x128 tile) ----------------
// epilogue: k-tile (blockIdx.y==1) stores exp(acc)
__global__ void __launch_bounds__(256) k_gemm_qkv(const float* __restrict__ W,
                                                  const float* __restrict__ X) {
    __shared__ unsigned As[128 * 36];   // [m][k] stride 36
    __shared__ unsigned Bs[32 * 136];   // [k][n] stride 136
    const int b    = blockIdx.z;
    const int mblk = blockIdx.y;
    const int m0   = mblk * 128;
    const int n0   = blockIdx.x * 128;
    const int tid  = threadIdx.x;
    const int lane = tid & 31;
    const int warp = tid >> 5;
    const int wm = warp >> 2, wn = warp & 3;     // 2 x 4 warp grid -> 64x32 per warp
    const float* Xb = X + (size_t)b * CH * NPIX;

    float acc[4][4][4];
    #pragma unroll
    for (int mt = 0; mt < 4; mt++)
        #pragma unroll
        for (int nt = 0; nt < 4; nt++)
            #pragma unroll
            for (int r = 0; r < 4; r++) acc[mt][nt][r] = 0.f;

    for (int k0 = 0; k0 < CH; k0 += 32) {
        #pragma unroll
        for (int l = 0; l < 4; l++) {        // A: 128 x 32
            int t = tid + l * 256;
            int m = t >> 3, k4 = (t & 7) * 4;
            float4 v = *reinterpret_cast<const float4*>(&W[(size_t)(m0 + m) * CH + k0 + k4]);
            As[m * 36 + k4 + 0] = f2tf(v.x);
            As[m * 36 + k4 + 1] = f2tf(v.y);
            As[m * 36 + k4 + 2] = f2tf(v.z);
            As[m * 36 + k4 + 3] = f2tf(v.w);
        }
        #pragma unroll
        for (int l = 0; l < 4; l++) {        // B: 32 x 128
            int t = tid + l * 256;
            int k = t >> 5, n4 = (t & 31) * 4;
            float4 v = *reinterpret_cast<const float4*>(&Xb[(size_t)(k0 + k) * NPIX + n0 + n4]);
            Bs[k * 136 + n4 + 0] = f2tf(v.x);
            Bs[k * 136 + n4 + 1] = f2tf(v.y);
            Bs[k * 136 + n4 + 2] = f2tf(v.z);
            Bs[k * 136 + n4 + 3] = f2tf(v.w);
        }
        __syncthreads();
        #pragma unroll
        for (int kk = 0; kk < 32; kk += 8) {
            unsigned a[4][4], bf[4][2];
            #pragma unroll
            for (int mt = 0; mt < 4; mt++) {
                int r0 = wm * 64 + mt * 16 + (lane >> 2);
                int c0 = kk + (lane & 3);
                a[mt][0] = As[r0 * 36 + c0];
                a[mt][1] = As[(r0 + 8) * 36 + c0];
                a[mt][2] = As[r0 * 36 + c0 + 4];
                a[mt][3] = As[(r0 + 8) * 36 + c0 + 4];
            }
            #pragma unroll
            for (int nt = 0; nt < 4; nt++) {
                int cc = wn * 32 + nt * 8 + (lane >> 2);
                int rr = kk + (lane & 3);
                bf[nt][0] = Bs[rr * 136 + cc];
                bf[nt][1] = Bs[(rr + 4) * 136 + cc];
            }
            #pragma unroll
            for (int mt = 0; mt < 4; mt++)
                #pragma unroll
                for (int nt = 0; nt < 4; nt++)
                    mma_tf32(acc[mt][nt], a[mt], bf[nt]);
        }
        __syncthreads();
    }

    float* out = g_qkv + (size_t)b * M3 * NPIX;
    const bool isK = (mblk == 1);
    #pragma unroll
    for (int mt = 0; mt < 4; mt++) {
        int row = m0 + wm * 64 + mt * 16 + (lane >> 2);
        #pragma unroll
        for (int nt = 0; nt < 4; nt++) {
            int col = n0 + wn * 32 + nt * 8 + (lane & 3) * 2;
            float2 v0 = make_float2(acc[mt][nt][0], acc[mt][nt][1]);
            float2 v1 = make_float2(acc[mt][nt][2], acc[mt][nt][3]);
            if (isK) { v0.x = expf(v0.x); v0.y = expf(v0.y);
                       v1.x = expf(v1.x); v1.y = expf(v1.y); }
            *reinterpret_cast<float2*>(&out[(size_t)row * NPIX + col])       = v0;
            *reinterpret_cast<float2*>(&out[(size_t)(row + 8) * NPIX + col]) = v1;
        }
    }
}

// ---------------- K2: q softmax over d (32), *scale, in-place ----------------
__global__ void k_qsoftmax() {
    int nt = blockIdx.x, h = blockIdx.y, b = blockIdx.z;
    int n = nt * 256 + threadIdx.x;
    float* base = g_qkv + ((size_t)b * M3 + h * HDIM) * NPIX + n;
    float v[HDIM];
    float mx = -1e30f;
    #pragma unroll
    for (int d = 0; d < HDIM; d++) { v[d] = base[(size_t)d * NPIX]; mx = fmaxf(mx, v[d]); }
    float s = 0.f;
    #pragma unroll
    for (int d = 0; d < HDIM; d++) { v[d] = expf(v[d] - mx); s += v[d]; }
    float inv = SCALE / s;
    #pragma unroll
    for (int d = 0; d < HDIM; d++) base[(size_t)d * NPIX] = v[d] * inv;
}

// ---------------- K3: per-chunk partials of S_kv, S_k (ek precomputed) ----------------
// block = (chunk, b). 256 threads: h = tid>>6; 8x8 grid of (d-quad, e-quad).
__global__ void __launch_bounds__(256) k_context() {
    __shared__ float S[256 * 33];   // local rows: 0..127 = ek(h*32+d), 128..255 = v(h*32+e)
    const int chunk = blockIdx.x;
    const int b     = blockIdx.y;
    const int tid   = threadIdx.x;
    const int h     = tid >> 6;
    const int local = tid & 63;
    const int d0 = (local >> 3) << 2;
    const int e0 = (local & 7) << 2;
    const int n0 = chunk * 256;

    float acc[4][4];
    float ksum[4] = {0.f, 0.f, 0.f, 0.f};
    #pragma unroll
    for (int i = 0; i < 4; i++)
        #pragma unroll
        for (int j = 0; j < 4; j++) acc[i][j] = 0.f;

    for (int sub = 0; sub < 8; sub++) {
        int c0 = n0 + sub * 32;
        #pragma unroll
        for (int l = 0; l < 8; l++) {          // 256 rows x 32 cols
            int t = tid + l * 256;
            int r = t >> 3, c4 = (t & 7) * 4;
            float4 v = *reinterpret_cast<const float4*>(
                &g_qkv[((size_t)b * M3 + 128 + r) * NPIX + c0 + c4]);
            float* s = &S[r * 33 + c4];
            s[0] = v.x; s[1] = v.y; s[2] = v.z; s[3] = v.w;
        }
        __syncthreads();
        #pragma unroll 4
        for (int c = 0; c < 32; c++) {
            float ek[4], vv[4];
            #pragma unroll
            for (int i = 0; i < 4; i++) ek[i] = S[(h * HDIM + d0 + i) * 33 + c];
            #pragma unroll
            for (int j = 0; j < 4; j++) vv[j] = S[(128 + h * HDIM + e0 + j) * 33 + c];
            #pragma unroll
            for (int i = 0; i < 4; i++)
                #pragma unroll
                for (int j = 0; j < 4; j++)
                    acc[i][j] = fmaf(ek[i], vv[j], acc[i][j]);
            if ((local & 7) == 0) {
                #pragma unroll
                for (int i = 0; i < 4; i++) ksum[i] += ek[i];
            }
        }
        __syncthreads();
    }
    size_t pbase = (((size_t)chunk * BATCH + b) * NHEAD + h) * (HDIM * HDIM);
    #pragma unroll
    for (int i = 0; i < 4; i++)
        #pragma unroll
        for (int j = 0; j < 4; j++)
            g_skvp[pbase + (d0 + i) * HDIM + e0 + j] = acc[i][j];
    if ((local & 7) == 0) {
        size_t kb = (((size_t)chunk * BATCH + b) * NHEAD + h) * HDIM;
        #pragma unroll
        for (int i = 0; i < 4; i++) g_skp[kb + d0 + i] = ksum[i];
    }
}

// ---------------- K3b: reduce partials; M_b = w_out @ blockdiag(ctx^T) ----------------
__global__ void k_buildM(const float* __restrict__ Wout) {
    __shared__ float ctx[NHEAD * HDIM * HDIM];
    __shared__ float sk[NHEAD * HDIM];
    const int b = blockIdx.x;
    const int tid = threadIdx.x;
    if (tid < NHEAD * HDIM) {
        float s = 0.f;
        for (int c = 0; c < NCHUNK; c++)
            s += g_skp[((size_t)c * BATCH + b) * NHEAD * HDIM + tid];
        sk[tid] = s;
    }
    __syncthreads();
    for (int i = tid; i < NHEAD * HDIM * HDIM; i += 256) {
        float s = 0.f;
        for (int c = 0; c < NCHUNK; c++)
            s += g_skvp[((size_t)c * BATCH + b) * (NHEAD * HDIM * HDIM) + i];
        ctx[i] = s / sk[i >> 5];
    }
    __syncthreads();
    for (int i = tid; i < CH * CH; i += 256) {
        int c = i >> 7, dg = i & 127;
        int h = dg >> 5, d = dg & 31;
        const float* wrow = Wout + (size_t)c * CH + h * HDIM;
        const float* cr   = ctx + (h * HDIM + d) * HDIM;
        float acc = 0.f;
        #pragma unroll
        for (int e = 0; e < HDIM; e++) acc = fmaf(wrow[e], cr[e], acc);
        g_M[(size_t)b * CH * CH + i] = acc;
    }
}

// ---------------- K4: pre = M_b @ q_sm + bias ; stats (tf32 mma) ----------------
__global__ void __launch_bounds__(256) k_proj(const float* __restrict__ Bias) {
    __shared__ unsigned As[128 * 36];
    __shared__ unsigned Bs[32 * 136];
    __shared__ float s1[8], s2[8];
    const int b   = blockIdx.y;
    const int n0  = blockIdx.x * 128;
    const int tid = threadIdx.x;
    const int lane = tid & 31;
    const int warp = tid >> 5;
    const int wm = warp >> 2, wn = warp & 3;
    const float* W  = g_M + (size_t)b * CH * CH;
    const float* Qb = g_qkv + (size_t)b * M3 * NPIX;

    float acc[4][4][4];
    #pragma unroll
    for (int mt = 0; mt < 4; mt++)
        #pragma unroll
        for (int nt = 0; nt < 4; nt++)
            #pragma unroll
            for (int r = 0; r < 4; r++) acc[mt][nt][r] = 0.f;

    for (int k0 = 0; k0 < CH; k0 += 32) {
        #pragma unroll
        for (int l = 0; l < 4; l++) {
            int t = tid + l * 256;
            int m = t >> 3, k4 = (t & 7) * 4;
            float4 v = *reinterpret_cast<const float4*>(&W[(size_t)m * CH + k0 + k4]);
            As[m * 36 + k4 + 0] = f2tf(v.x);
            As[m * 36 + k4 + 1] = f2tf(v.y);
            As[m * 36 + k4 + 2] = f2tf(v.z);
            As[m * 36 + k4 + 3] = f2tf(v.w);
        }
        #pragma unroll
        for (int l = 0; l < 4; l++) {
            int t = tid + l * 256;
            int k = t >> 5, n4 = (t & 31) * 4;
            float4 v = *reinterpret_cast<const float4*>(&Qb[(size_t)(k0 + k) * NPIX + n0 + n4]);
            Bs[k * 136 + n4 + 0] = f2tf(v.x);
            Bs[k * 136 + n4 + 1] = f2tf(v.y);
            Bs[k * 136 + n4 + 2] = f2tf(v.z);
            Bs[k * 136 + n4 + 3] = f2tf(v.w);
        }
        __syncthreads();
        #pragma unroll
        for (int kk = 0; kk < 32; kk += 8) {
            unsigned a[4][4], bf[4][2];
            #pragma unroll
            for (int mt = 0; mt < 4; mt++) {
                int r0 = wm * 64 + mt * 16 + (lane >> 2);
                int c0 = kk + (lane & 3);
                a[mt][0] = As[r0 * 36 + c0];
                a[mt][1] = As[(r0 + 8) * 36 + c0];
                a[mt][2] = As[r0 * 36 + c0 + 4];
                a[mt][3] = As[(r0 + 8) * 36 + c0 + 4];
            }
            #pragma unroll
            for (int nt = 0; nt < 4; nt++) {
                int cc = wn * 32 + nt * 8 + (lane >> 2);
                int rr = kk + (lane & 3);
                bf[nt][0] = Bs[rr * 136 + cc];
                bf[nt][1] = Bs[(rr + 4) * 136 + cc];
            }
            #pragma unroll
            for (int mt = 0; mt < 4; mt++)
                #pragma unroll
                for (int nt = 0; nt < 4; nt++)
                    mma_tf32(acc[mt][nt], a[mt], bf[nt]);
        }
        __syncthreads();
    }

    float* out = g_pre + (size_t)b * CH * NPIX;
    float lsum = 0.f, lsq = 0.f;
    #pragma unroll
    for (int mt = 0; mt < 4; mt++) {
        int row = wm * 64 + mt * 16 + (lane >> 2);
        float bias0 = __ldg(&Bias[row]);
        float bias1 = __ldg(&Bias[row + 8]);
        #pragma unroll
        for (int nt = 0; nt < 4; nt++) {
            int col = n0 + wn * 32 + nt * 8 + (lane & 3) * 2;
            float2 v0 = make_float2(acc[mt][nt][0] + bias0, acc[mt][nt][1] + bias0);
            float2 v1 = make_float2(acc[mt][nt][2] + bias1, acc[mt][nt][3] + bias1);
            lsum += v0.x + v0.y + v1.x + v1.y;
            lsq = fmaf(v0.x, v0.x, lsq); lsq = fmaf(v0.y, v0.y, lsq);
            lsq = fmaf(v1.x, v1.x, lsq); lsq = fmaf(v1.y, v1.y, lsq);
            *reinterpret_cast<float2*>(&out[(size_t)row * NPIX + col])       = v0;
            *reinterpret_cast<float2*>(&out[(size_t)(row + 8) * NPIX + col]) = v1;
        }
    }
    #pragma unroll
    for (int off = 16; off > 0; off >>= 1) {
        lsum += __shfl_down_sync(0xffffffffu, lsum, off);
        lsq  += __shfl_down_sync(0xffffffffu, lsq,  off);
    }
    if (lane == 0) { s1[warp] = lsum; s2[warp] = lsq; }
    __syncthreads();
    if (tid == 0) {
        float t1 = 0.f, t2 = 0.f;
        #pragma unroll
        for (int w = 0; w < 8; w++) { t1 += s1[w]; t2 += s2[w]; }
        atomicAdd(&g_stats[b * 2 + 0], t1);
        atomicAdd(&g_stats[b * 2 + 1], t2);
    }
}

// ---------------- K5: LayerNorm normalize + affine ----------------
__global__ void k_norm(const float* __restrict__ gnw, const float* __restrict__ gnb,
                       float* __restrict__ out) {
    size_t i4 = (size_t)blockIdx.x * 256 + threadIdx.x;
    size_t idx = i4 * 4;
    const float invCN = 1.f / (float)(CH * NPIX);
    int b = (int)(idx / ((size_t)CH * NPIX));
    int c = (int)((idx / NPIX) & (CH - 1));
    float mean = g_stats[b * 2 + 0] * invCN;
    float var  = g_stats[b * 2 + 1] * invCN - mean * mean;
    float rstd = rsqrtf(var + EPSV);
    float w  = gnw[c] * rstd;
    float bb = gnb[c] - mean * w;
    float4 v = *reinterpret_cast<const float4*>(g_pre + idx);
    v.x = fmaf(v.x, w, bb);
    v.y = fmaf(v.y, w, bb);
    v.z = fmaf(v.z, w, bb);
    v.w = fmaf(v.w, w, bb);
    *reinterpret_cast<float4*>(out + idx) = v;
}

// ---------------- launcher ----------------
extern "C" void kernel_launch(void* const* d_in, const int* in_sizes, int n_in,
                              void* d_out, int out_size) {
    const float* x     = (const float*)d_in[0];
    const float* w_qkv = (const float*)d_in[1];
    const float* w_out = (const float*)d_in[2];
    const float* b_out = (const float*)d_in[3];
    const float* gnw   = (const float*)d_in[4];
    const float* gnb   = (const float*)d_in[5];

    k_zero<<<1, 32>>>();
    k_gemm_qkv<<<dim3(32, 3, 16), 256>>>(w_qkv, x);
    k_qsoftmax<<<dim3(16, 4, 16), 256>>>();
    k_context<<<dim3(NCHUNK, 16), 256>>>();
    k_buildM<<<16, 256>>>(w_out);
    k_proj<<<dim3(32, 16), 256>>>(b_out);
    k_norm<<<8192, 256>>>(gnw, gnb, (float*)d_out);
}